// round 1
// baseline (speedup 1.0000x reference)
#include <cuda_runtime.h>

#define NQ 10
#define NDIM 1024
#define DEPTH 6
#define NF 1024
#define NC 10
#define NTHREADS 512

// Precomputed Rot matrices: [l][q][4] (u00,u01,u10,u11) as float2 (re,im)
__device__ float2 g_rot[DEPTH * NQ * 4];

__global__ void build_rot_kernel(const float* __restrict__ weights) {
    int t = threadIdx.x;
    if (t >= DEPTH * NQ) return;
    float phi = weights[t * 3 + 0];
    float theta = weights[t * 3 + 1];
    float omega = weights[t * 3 + 2];
    float c, s;
    sincosf(0.5f * theta, &s, &c);
    float sp, cp, sm, cm;
    sincosf(-0.5f * (phi + omega), &sp, &cp);  // ep = cp + i*sp
    sincosf(-0.5f * (phi - omega), &sm, &cm);  // em = cm + i*sm
    // u00 = ep*c
    g_rot[t * 4 + 0] = make_float2(cp * c, sp * c);
    // u01 = -conj(em)*s = (-cm*s, sm*s)
    g_rot[t * 4 + 1] = make_float2(-cm * s, sm * s);
    // u10 = em*s
    g_rot[t * 4 + 2] = make_float2(cm * s, sm * s);
    // u11 = conj(ep)*c = (cp*c, -sp*c)
    g_rot[t * 4 + 3] = make_float2(cp * c, -sp * c);
}

__global__ __launch_bounds__(NTHREADS, 3)
void vqc_kernel(const float* __restrict__ x,
                const float* __restrict__ Wp,
                const float* __restrict__ Wout,
                const float* __restrict__ bout,
                float* __restrict__ out) {
    __shared__ float re[NDIM];
    __shared__ float im[NDIM];
    __shared__ float mats[DEPTH * NQ * 8];
    __shared__ float warpred[NQ * 16];
    __shared__ float angc[NQ], angs[NQ];
    __shared__ float exps[NQ];

    const int b = blockIdx.x;
    const int t = threadIdx.x;
    const int lane = t & 31;
    const int w = t >> 5;

    // Stage rot matrices in shared (480 floats)
    if (t < DEPTH * NQ * 8) mats[t] = reinterpret_cast<const float*>(g_rot)[t];

    // ---- angles: 10 dot products of x[b] (1024) with W_proj rows ----
    const float* xr = x + (size_t)b * NF;
    float x0 = xr[t];
    float x1 = xr[t + 512];
    float acc[NQ];
#pragma unroll
    for (int q = 0; q < NQ; q++) {
        acc[q] = x0 * Wp[q * NF + t] + x1 * Wp[q * NF + t + 512];
    }
#pragma unroll
    for (int off = 16; off > 0; off >>= 1) {
#pragma unroll
        for (int q = 0; q < NQ; q++)
            acc[q] += __shfl_down_sync(0xffffffffu, acc[q], off);
    }
    if (lane == 0) {
#pragma unroll
        for (int q = 0; q < NQ; q++) warpred[q * 16 + w] = acc[q];
    }
    __syncthreads();
    if (t < NQ) {
        float s = 0.0f;
#pragma unroll
        for (int ww = 0; ww < 16; ww++) s += warpred[t * 16 + ww];
        float ang = tanhf(s) * 1.5707963267948966f;  // * pi/2
        float cc, ss;
        sincosf(0.5f * ang, &ss, &cc);
        angc[t] = cc;
        angs[t] = ss;
    }
    __syncthreads();

    // ---- init statevector: product state from RY encoding ----
#pragma unroll
    for (int k = 0; k < 2; k++) {
        int m = t + k * 512;
        float v = 1.0f;
#pragma unroll
        for (int q = 0; q < NQ; q++) v *= ((m >> q) & 1) ? angs[q] : angc[q];
        re[m] = v;
        im[m] = 0.0f;
    }
    __syncthreads();

    // ---- layers ----
#pragma unroll
    for (int l = 0; l < DEPTH; l++) {
        // 10 single-qubit Rot gates
#pragma unroll
        for (int q = 0; q < NQ; q++) {
            const float* u = &mats[(l * NQ + q) * 8];
            float u00r = u[0], u00i = u[1], u01r = u[2], u01i = u[3];
            float u10r = u[4], u10i = u[5], u11r = u[6], u11i = u[7];
            int low = t & ((1 << q) - 1);
            int i0 = ((t >> q) << (q + 1)) | low;
            int i1 = i0 | (1 << q);
            float a0r = re[i0], a0i = im[i0];
            float a1r = re[i1], a1i = im[i1];
            float n0r = u00r * a0r - u00i * a0i + u01r * a1r - u01i * a1i;
            float n0i = u00r * a0i + u00i * a0r + u01r * a1i + u01i * a1r;
            float n1r = u10r * a0r - u10i * a0i + u11r * a1r - u11i * a1i;
            float n1i = u10r * a0i + u10i * a0r + u11r * a1i + u11i * a1r;
            re[i0] = n0r; im[i0] = n0i;
            re[i1] = n1r; im[i1] = n1i;
            __syncthreads();
        }
        // CNOT ring (range r = l+1) as one composed permutation:
        // psi_new[j] = psi_old[f_0(f_1(...f_9(j)))] applied innermost-first (i=9..0)
        const int r = l + 1;
        int j0 = t, j1 = t + 512;
        int s0 = j0, s1 = j1;
#pragma unroll
        for (int i = NQ - 1; i >= 0; i--) {
            int tt = i + r;
            if (tt >= NQ) tt -= NQ;
            s0 ^= ((s0 >> i) & 1) << tt;
            s1 ^= ((s1 >> i) & 1) << tt;
        }
        float v0r = re[s0], v0i = im[s0];
        float v1r = re[s1], v1i = im[s1];
        __syncthreads();
        re[j0] = v0r; im[j0] = v0i;
        re[j1] = v1r; im[j1] = v1i;
        __syncthreads();
    }

    // ---- Z expectations ----
    float accz[NQ];
    {
        int m0 = t, m1 = t + 512;
        float p0 = re[m0] * re[m0] + im[m0] * im[m0];
        float p1 = re[m1] * re[m1] + im[m1] * im[m1];
#pragma unroll
        for (int q = 0; q < NQ; q++) {
            float c0 = ((m0 >> q) & 1) ? -p0 : p0;
            float c1 = ((m1 >> q) & 1) ? -p1 : p1;
            accz[q] = c0 + c1;
        }
    }
#pragma unroll
    for (int off = 16; off > 0; off >>= 1) {
#pragma unroll
        for (int q = 0; q < NQ; q++)
            accz[q] += __shfl_down_sync(0xffffffffu, accz[q], off);
    }
    __syncthreads();  // warpred reuse
    if (lane == 0) {
#pragma unroll
        for (int q = 0; q < NQ; q++) warpred[q * 16 + w] = accz[q];
    }
    __syncthreads();
    if (t < NQ) {
        float s = 0.0f;
#pragma unroll
        for (int ww = 0; ww < 16; ww++) s += warpred[t * 16 + ww];
        exps[t] = s;
    }
    __syncthreads();

    // ---- linear head ----
    if (t < NC) {
        float o = bout[t];
#pragma unroll
        for (int q = 0; q < NQ; q++) o += exps[q] * Wout[t * NQ + q];
        out[(size_t)b * NC + t] = o;
    }
}

extern "C" void kernel_launch(void* const* d_in, const int* in_sizes, int n_in,
                              void* d_out, int out_size) {
    const float* x = (const float*)d_in[0];       // (8192, 1024)
    const float* W_proj = (const float*)d_in[1];  // (10, 1024)
    const float* weights = (const float*)d_in[2]; // (6, 10, 3)
    const float* W_out = (const float*)d_in[3];   // (10, 10)
    const float* b_out = (const float*)d_in[4];   // (10,)
    float* out = (float*)d_out;                   // (8192, 10)

    build_rot_kernel<<<1, 64>>>(weights);
    vqc_kernel<<<8192, NTHREADS>>>(x, W_proj, W_out, b_out, out);
}

// round 2
// speedup vs baseline: 2.1426x; 2.1426x over previous
#include <cuda_runtime.h>

#define NQ 10
#define DEPTH 6
#define NF 1024
#define NC 10
#define MAXB 8192

// Precomputed Rot matrices: [l][q] -> two float4: (u00r,u00i,u01r,u01i),(u10r,u10i,u11r,u11i)
__device__ float4 g_rot4[DEPTH * NQ * 2];
// Precomputed half-angle trig per sample/qubit: (cos, sin)
__device__ float2 g_trig[MAXB * NQ];

__global__ void build_rot_kernel(const float* __restrict__ w) {
    int t = threadIdx.x;
    if (t >= DEPTH * NQ) return;
    float phi = w[t * 3 + 0], theta = w[t * 3 + 1], omega = w[t * 3 + 2];
    float c, s;
    sincosf(0.5f * theta, &s, &c);
    float sp, cp, sm, cm;
    sincosf(-0.5f * (phi + omega), &sp, &cp);  // ep
    sincosf(-0.5f * (phi - omega), &sm, &cm);  // em
    // u00=ep*c  u01=-conj(em)*s  u10=em*s  u11=conj(ep)*c
    g_rot4[t * 2 + 0] = make_float4(cp * c, sp * c, -cm * s, sm * s);
    g_rot4[t * 2 + 1] = make_float4(cm * s, sm * s, cp * c, -sp * c);
}

// one warp per sample: 10 dot products (len 1024) -> tanh -> half-angle trig
__global__ __launch_bounds__(256) void proj_kernel(const float* __restrict__ x,
                                                   const float* __restrict__ Wp, int B) {
    int warp = threadIdx.x >> 5, lane = threadIdx.x & 31;
    int b = blockIdx.x * 8 + warp;
    if (b >= B) return;
    const float4* xv = (const float4*)(x + (size_t)b * NF);
    float acc[NQ];
#pragma unroll
    for (int q = 0; q < NQ; q++) acc[q] = 0.f;
#pragma unroll
    for (int it = 0; it < 8; it++) {
        float4 xx = xv[it * 32 + lane];
#pragma unroll
        for (int q = 0; q < NQ; q++) {
            float4 ww = __ldg(&((const float4*)(Wp + q * NF))[it * 32 + lane]);
            acc[q] += xx.x * ww.x + xx.y * ww.y + xx.z * ww.z + xx.w * ww.w;
        }
    }
#pragma unroll
    for (int off = 16; off > 0; off >>= 1)
#pragma unroll
        for (int q = 0; q < NQ; q++) acc[q] += __shfl_xor_sync(0xffffffffu, acc[q], off);
    if (lane < NQ) {
        float v = acc[0];
#pragma unroll
        for (int q = 1; q < NQ; q++)
            if (lane == q) v = acc[q];
        float half = tanhf(v) * 0.78539816339744831f;  // (pi/2)/2
        float cc, ss;
        sincosf(half, &ss, &cc);
        g_trig[b * NQ + lane] = make_float2(cc, ss);
    }
}

// CNOT ring for range R, applied as sequential conditional swaps.
// qubit q = bit q of amplitude index m = r*32 + lane (lane bits = q0..4, reg bits = q5..9)
template <int R>
__device__ __forceinline__ void cnot_layer(float (&ar)[32], float (&ai)[32], int lane) {
#pragma unroll
    for (int i = 0; i < NQ; i++) {
        const int c = i;
        const int t = (i + R) % NQ;
        if (c < 5 && t < 5) {
            // control = lane bit, target = lane bit: shuffle + select
            bool ctrl = (lane >> c) & 1;
#pragma unroll
            for (int r = 0; r < 32; r++) {
                float pr_ = __shfl_xor_sync(0xffffffffu, ar[r], 1 << t);
                float pi_ = __shfl_xor_sync(0xffffffffu, ai[r], 1 << t);
                ar[r] = ctrl ? pr_ : ar[r];
                ai[r] = ctrl ? pi_ : ai[r];
            }
        } else if (c < 5 && t >= 5) {
            // control = lane bit, target = reg bit: predicated register swap
            const int tb = 1 << (t - 5);
            bool ctrl = (lane >> c) & 1;
#pragma unroll
            for (int r0 = 0; r0 < 32; r0++)
                if (!(r0 & tb)) {
                    const int r1 = r0 | tb;
                    float t0 = ar[r0], t1 = ai[r0];
                    ar[r0] = ctrl ? ar[r1] : ar[r0];
                    ai[r0] = ctrl ? ai[r1] : ai[r0];
                    ar[r1] = ctrl ? t0 : ar[r1];
                    ai[r1] = ctrl ? t1 : ai[r1];
                }
        } else if (c >= 5 && t < 5) {
            // control = reg bit (compile-time), target = lane bit: unconditional shuffle on half the regs
            const int cb = 1 << (c - 5);
#pragma unroll
            for (int r = 0; r < 32; r++)
                if (r & cb) {
                    ar[r] = __shfl_xor_sync(0xffffffffu, ar[r], 1 << t);
                    ai[r] = __shfl_xor_sync(0xffffffffu, ai[r], 1 << t);
                }
        } else {
            // both reg bits: compile-time register swap (free SSA rename)
            const int cb = 1 << (c - 5), tb = 1 << (t - 5);
#pragma unroll
            for (int r0 = 0; r0 < 32; r0++)
                if ((r0 & cb) && !(r0 & tb)) {
                    const int r1 = r0 | tb;
                    float tmp = ar[r0]; ar[r0] = ar[r1]; ar[r1] = tmp;
                    tmp = ai[r0]; ai[r0] = ai[r1]; ai[r1] = tmp;
                }
        }
    }
}

__global__ __launch_bounds__(256, 2) void vqc_kernel(const float* __restrict__ Wout,
                                                     const float* __restrict__ bout,
                                                     float* __restrict__ out, int B) {
    const int warp = threadIdx.x >> 5, lane = threadIdx.x & 31;
    const int b = blockIdx.x * 8 + warp;
    if (b >= B) return;

    // ---- init: RY product state ----
    float tc[NQ], ts[NQ];
#pragma unroll
    for (int q = 0; q < NQ; q++) {
        float2 v = g_trig[b * NQ + q];
        tc[q] = v.x;
        ts[q] = v.y;
    }
    float pl = 1.f;
#pragma unroll
    for (int q = 0; q < 5; q++) pl *= ((lane >> q) & 1) ? ts[q] : tc[q];
    float ar[32], ai[32];
#pragma unroll
    for (int r = 0; r < 32; r++) {
        float pr_ = pl;
#pragma unroll
        for (int j = 0; j < 5; j++) pr_ *= ((r >> j) & 1) ? ts[5 + j] : tc[5 + j];
        ar[r] = pr_;
        ai[r] = 0.f;
    }

    // ---- layers ----
#pragma unroll 1
    for (int l = 0; l < DEPTH; l++) {
#pragma unroll
        for (int q = 0; q < NQ; q++) {
            float4 A = __ldg(&g_rot4[(l * NQ + q) * 2]);      // u00, u01
            float4 Bm = __ldg(&g_rot4[(l * NQ + q) * 2 + 1]); // u10, u11
            if (q >= 5) {
                const int jb = 1 << (q - 5);
#pragma unroll
                for (int r0 = 0; r0 < 32; r0++)
                    if (!(r0 & jb)) {
                        const int r1 = r0 | jb;
                        float a0r = ar[r0], a0i = ai[r0];
                        float a1r = ar[r1], a1i = ai[r1];
                        ar[r0] = A.x * a0r - A.y * a0i + A.z * a1r - A.w * a1i;
                        ai[r0] = A.x * a0i + A.y * a0r + A.z * a1i + A.w * a1r;
                        ar[r1] = Bm.x * a0r - Bm.y * a0i + Bm.z * a1r - Bm.w * a1i;
                        ai[r1] = Bm.x * a0i + Bm.y * a0r + Bm.z * a1i + Bm.w * a1r;
                    }
            } else {
                bool hi = (lane >> q) & 1;
                float car = hi ? Bm.z : A.x, cai = hi ? Bm.w : A.y;
                float cbr = hi ? Bm.x : A.z, cbi = hi ? Bm.y : A.w;
#pragma unroll
                for (int r = 0; r < 32; r++) {
                    float pr_ = __shfl_xor_sync(0xffffffffu, ar[r], 1 << q);
                    float pi_ = __shfl_xor_sync(0xffffffffu, ai[r], 1 << q);
                    float mr = ar[r], mi = ai[r];
                    ar[r] = car * mr - cai * mi + cbr * pr_ - cbi * pi_;
                    ai[r] = car * mi + cai * mr + cbr * pi_ + cbi * pr_;
                }
            }
        }
        switch (l) {
            case 0: cnot_layer<1>(ar, ai, lane); break;
            case 1: cnot_layer<2>(ar, ai, lane); break;
            case 2: cnot_layer<3>(ar, ai, lane); break;
            case 3: cnot_layer<4>(ar, ai, lane); break;
            case 4: cnot_layer<5>(ar, ai, lane); break;
            default: cnot_layer<6>(ar, ai, lane); break;
        }
    }

    // ---- Z expvals ----
    float S = 0.f, T0 = 0.f, T1 = 0.f, T2 = 0.f, T3 = 0.f, T4 = 0.f;
#pragma unroll
    for (int r = 0; r < 32; r++) {
        float p = ar[r] * ar[r] + ai[r] * ai[r];
        S += p;
        T0 += (r & 1) ? -p : p;
        T1 += (r & 2) ? -p : p;
        T2 += (r & 4) ? -p : p;
        T3 += (r & 8) ? -p : p;
        T4 += (r & 16) ? -p : p;
    }
    float e[NQ];
#pragma unroll
    for (int q = 0; q < 5; q++) e[q] = ((lane >> q) & 1) ? -S : S;
    e[5] = T0; e[6] = T1; e[7] = T2; e[8] = T3; e[9] = T4;
#pragma unroll
    for (int off = 16; off > 0; off >>= 1)
#pragma unroll
        for (int q = 0; q < NQ; q++) e[q] += __shfl_xor_sync(0xffffffffu, e[q], off);

    // ---- linear head (all lanes hold all 10 exps after xor-butterfly) ----
    if (lane < NC) {
        float o = __ldg(&bout[lane]);
#pragma unroll
        for (int q = 0; q < NQ; q++) o += e[q] * __ldg(&Wout[lane * NQ + q]);
        out[(size_t)b * NC + lane] = o;
    }
}

extern "C" void kernel_launch(void* const* d_in, const int* in_sizes, int n_in,
                              void* d_out, int out_size) {
    const float* x = (const float*)d_in[0];        // (B, 1024)
    const float* W_proj = (const float*)d_in[1];   // (10, 1024)
    const float* weights = (const float*)d_in[2];  // (6, 10, 3)
    const float* W_out = (const float*)d_in[3];    // (10, 10)
    const float* b_out = (const float*)d_in[4];    // (10,)
    float* out = (float*)d_out;                    // (B, 10)

    int B = in_sizes[0] / NF;
    int nblk = (B + 7) / 8;

    build_rot_kernel<<<1, 64>>>(weights);
    proj_kernel<<<nblk, 256>>>(x, W_proj, B);
    vqc_kernel<<<nblk, 256>>>(W_out, b_out, out, B);
}